// round 17
// baseline (speedup 1.0000x reference)
#include <cuda_runtime.h>
#include <cstdint>

#define NSEQ   1605
#define DIMF   1024
#define NH     16
#define DH     64
#define HWLEN  1600
#define PREFIX 5
#define NPAD   1664   // 26 * 64
#define NSPLIT 2
#define NKT_TOT 51
#define NKT0   26

// ---- scratch (device globals; zero-init; padded regions never written) ----
__device__ float g_q[(size_t)NH * NPAD * DH];
__device__ float g_k[(size_t)NH * NPAD * DH];
__device__ float g_v[(size_t)NH * NPAD * DH];
__device__ float  g_part[(size_t)NSPLIT * NH * NPAD * DH];
__device__ float2 g_ml[(size_t)NSPLIT * NH * NPAD];

// packed bf16x2 hi/lo arrays (pairs along the K/feature dim)
__device__ uint32_t g_xh[(size_t)1664 * 512],  g_xl[(size_t)1664 * 512];
__device__ uint32_t g_wqh[(size_t)3072 * 512], g_wql[(size_t)3072 * 512];
__device__ uint32_t g_wph[(size_t)1024 * 512], g_wpl[(size_t)1024 * 512];
__device__ uint32_t g_qph[(size_t)NH * NPAD * 32], g_qpl[(size_t)NH * NPAD * 32];
__device__ uint32_t g_kph[(size_t)NH * NPAD * 32], g_kpl[(size_t)NH * NPAD * 32];
__device__ uint32_t g_ath[(size_t)1664 * 512], g_atl[(size_t)1664 * 512];

// ============================================================
// helpers
// ============================================================
__device__ __forceinline__ uint32_t cvta_s(const void* p) {
    uint32_t a;
    asm("{ .reg .u64 t; cvta.to.shared.u64 t, %1; cvt.u32.u64 %0, t; }"
        : "=r"(a) : "l"(p));
    return a;
}

#define MMA_BF16(d, a0, a1, a2, a3, b0, b1) \
    asm volatile("mma.sync.aligned.m16n8k16.row.col.f32.bf16.bf16.f32 " \
        "{%0,%1,%2,%3}, {%4,%5,%6,%7}, {%8,%9}, {%0,%1,%2,%3};" \
        : "+f"((d)[0]), "+f"((d)[1]), "+f"((d)[2]), "+f"((d)[3]) \
        : "r"(a0), "r"(a1), "r"(a2), "r"(a3), "r"(b0), "r"(b1))

#define LDSM_X4(r0, r1, r2, r3, addr) \
    asm volatile("ldmatrix.sync.aligned.m8n8.x4.shared.b16 {%0,%1,%2,%3}, [%4];" \
        : "=r"(r0), "=r"(r1), "=r"(r2), "=r"(r3) : "r"(addr))

__device__ __forceinline__ uint32_t pack_bf16x2(float lo, float hi) {
    uint32_t w;
    asm("cvt.rn.bf16x2.f32 %0, %1, %2;" : "=r"(w) : "f"(hi), "f"(lo));
    return w;
}
__device__ __forceinline__ float lo_bf16(uint32_t w) { return __uint_as_float(w << 16); }
__device__ __forceinline__ float hi_bf16(uint32_t w) { return __uint_as_float(w & 0xFFFF0000u); }

__device__ __forceinline__ void split2(float e, float o, uint32_t& h, uint32_t& l) {
    h = pack_bf16x2(e, o);
    l = pack_bf16x2(e - lo_bf16(h), o - hi_bf16(h));
}

extern __shared__ float dynsm[];

// ============================================================
// presplit: x, Wqkv, Wproj -> packed hi/lo (one uint4 per thread)
// ============================================================
#define PS_NX (1605 * 128)
#define PS_NQ (3072 * 128)
#define PS_NP (1024 * 128)
#define PS_TOT (PS_NX + PS_NQ + PS_NP)

__global__ void presplit_kern(const float* __restrict__ x,
                              const float* __restrict__ Wqkv,
                              const float* __restrict__ Wproj)
{
    const int t = blockIdx.x * blockDim.x + threadIdx.x;
    if (t >= PS_TOT) return;
    const float4* src; uint32_t* dh; uint32_t* dl; size_t gi;
    if (t < PS_NX)            { src = (const float4*)x;     dh = g_xh;  dl = g_xl;  gi = t; }
    else if (t < PS_NX+PS_NQ) { src = (const float4*)Wqkv;  dh = g_wqh; dl = g_wql; gi = t - PS_NX; }
    else                      { src = (const float4*)Wproj; dh = g_wph; dl = g_wpl; gi = t - PS_NX - PS_NQ; }
    const float4 a = src[2 * gi];
    const float4 b = src[2 * gi + 1];
    uint32_t h0,l0,h1,l1,h2,l2,h3,l3;
    split2(a.x, a.y, h0, l0);
    split2(a.z, a.w, h1, l1);
    split2(b.x, b.y, h2, l2);
    split2(b.z, b.w, h3, l3);
    ((uint4*)dh)[gi] = make_uint4(h0, h1, h2, h3);
    ((uint4*)dl)[gi] = make_uint4(l0, l1, l2, l3);
}

// ============================================================
// bf16x3 GEMM mainloop on PRE-PACKED inputs (2-stage, pure copy).
// MT=4 -> 128-row A tile; MT=2 -> 64-row. N tile 128, rows padded.
// ============================================================
#define BST 12

template<int MT>
__device__ __forceinline__ void gemm3bp(
    const uint4* __restrict__ Ah4, const uint4* __restrict__ Al4,
    const uint4* __restrict__ Bh4, const uint4* __restrict__ Bl4,
    int bm, int bn, uint32_t* __restrict__ smem, float acc[MT][4][4])
{
    constexpr int AR  = MT * 32;
    constexpr int TA  = AR * BST;
    constexpr int TB  = 128 * BST;
    constexpr int BUF = 2 * TA + 2 * TB;

    const int tid = threadIdx.x;
    const int wid = tid >> 5, lane = tid & 31;
    const int warp_m = wid & 1, warp_n = wid >> 1;
    const int ra = tid >> 1;            // row for A and B loaders
    const int ua = tid & 1;             // which uint4 of the chunk

    const uint32_t smb = cvta_s(smem);
    const int a_lm = (warp_m * (MT * 16) + (lane & 15)) * BST + (lane >> 4) * 4;
    const int b_lm = (warp_n * 32 + (lane >> 4) * 8 + (lane & 7)) * BST
                     + ((lane >> 3) & 1) * 4;

    uint4 pah, pal, pbh, pbl;

#define GB_LOAD(k0) do { \
    if (MT == 4 || ra < AR) { \
        pah = Ah4[(size_t)(bm + ra) * 128 + ((k0) >> 3) + ua]; \
        pal = Al4[(size_t)(bm + ra) * 128 + ((k0) >> 3) + ua]; \
    } \
    pbh = Bh4[(size_t)(bn + ra) * 128 + ((k0) >> 3) + ua]; \
    pbl = Bl4[(size_t)(bn + ra) * 128 + ((k0) >> 3) + ua]; \
} while (0)

#define GB_STORE(bufw_) do { \
    if (MT == 4 || ra < AR) { \
        *(uint4*)(smem + (bufw_) + ra * BST + ua * 4) = pah; \
        *(uint4*)(smem + (bufw_) + TA + ra * BST + ua * 4) = pal; \
    } \
    *(uint4*)(smem + (bufw_) + 2 * TA + ra * BST + ua * 4) = pbh; \
    *(uint4*)(smem + (bufw_) + 2 * TA + TB + ra * BST + ua * 4) = pbl; \
} while (0)

    GB_LOAD(0);
    GB_STORE(0);
    __syncthreads();

    for (int c = 0; c < 64; ++c) {
        const int bufw = (c & 1) * BUF;
        if (c < 63) GB_LOAD((c + 1) * 16);

        uint32_t ah[MT][4], al[MT][4];
#pragma unroll
        for (int mt = 0; mt < MT; ++mt) {
            LDSM_X4(ah[mt][0], ah[mt][1], ah[mt][2], ah[mt][3],
                    smb + (uint32_t)(bufw + a_lm + mt * 16 * BST) * 4u);
            LDSM_X4(al[mt][0], al[mt][1], al[mt][2], al[mt][3],
                    smb + (uint32_t)(bufw + TA + a_lm + mt * 16 * BST) * 4u);
        }
#pragma unroll
        for (int ntp = 0; ntp < 2; ++ntp) {
            uint32_t bh0, bh1, bh2, bh3, bl0, bl1, bl2, bl3;
            LDSM_X4(bh0, bh1, bh2, bh3,
                    smb + (uint32_t)(bufw + 2 * TA + b_lm + ntp * 16 * BST) * 4u);
            LDSM_X4(bl0, bl1, bl2, bl3,
                    smb + (uint32_t)(bufw + 2 * TA + TB + b_lm + ntp * 16 * BST) * 4u);
#pragma unroll
            for (int mt = 0; mt < MT; ++mt) {
                MMA_BF16(acc[mt][2 * ntp], ah[mt][0], ah[mt][1], ah[mt][2], ah[mt][3], bh0, bh1);
                MMA_BF16(acc[mt][2 * ntp], ah[mt][0], ah[mt][1], ah[mt][2], ah[mt][3], bl0, bl1);
                MMA_BF16(acc[mt][2 * ntp], al[mt][0], al[mt][1], al[mt][2], al[mt][3], bh0, bh1);
                MMA_BF16(acc[mt][2 * ntp + 1], ah[mt][0], ah[mt][1], ah[mt][2], ah[mt][3], bh2, bh3);
                MMA_BF16(acc[mt][2 * ntp + 1], ah[mt][0], ah[mt][1], ah[mt][2], ah[mt][3], bl2, bl3);
                MMA_BF16(acc[mt][2 * ntp + 1], al[mt][0], al[mt][1], al[mt][2], al[mt][3], bh2, bh3);
            }
        }
        if (c < 63) GB_STORE(((c + 1) & 1) * BUF);
        __syncthreads();
    }
#undef GB_LOAD
#undef GB_STORE
}

#define GSMEM_128 (2 * (4 * 128 * BST) * 4)                 // 49152 B
#define GSMEM_64  (2 * (2 * 64 * BST + 2 * 128 * BST) * 4)  // 36864 B

// ============================================================
// MERGED qkv GEMM (MT=4): grid (24, 13)
// ============================================================
__global__ __launch_bounds__(256, 2) void gemm_qkv_kern()
{
    const int bm = blockIdx.y * 128;
    const int bn = blockIdx.x * 128;
    const int tid = threadIdx.x;
    const int wid = tid >> 5, lane = tid & 31;
    const int warp_m = wid & 1, warp_n = wid >> 1;
    const int grp = lane >> 2, tig = lane & 3;

    float acc[4][4][4];
#pragma unroll
    for (int a = 0; a < 4; a++)
#pragma unroll
        for (int b = 0; b < 4; b++)
#pragma unroll
            for (int cc = 0; cc < 4; cc++) acc[a][b][cc] = 0.0f;

    gemm3bp<4>((const uint4*)g_xh, (const uint4*)g_xl,
               (const uint4*)g_wqh, (const uint4*)g_wql,
               bm, bn, (uint32_t*)dynsm, acc);

    const int s = bn >> 10;
    float* __restrict__ dst = (s == 0) ? g_q : (s == 1) ? g_k : g_v;
    const float scale = (s == 0) ? 0.125f : 1.0f;

#pragma unroll
    for (int mt = 0; mt < 4; ++mt)
#pragma unroll
        for (int half = 0; half < 2; ++half) {
            const int row = bm + warp_m * 64 + mt * 16 + grp + half * 8;
            if (row >= NSEQ) continue;
#pragma unroll
            for (int nt = 0; nt < 4; ++nt) {
                const int col = bn + warp_n * 32 + nt * 8 + tig * 2;
                const int h = (col & 1023) >> 6;
                const int d = col & 63;
                float2 v;
                v.x = acc[mt][nt][half * 2 + 0] * scale;
                v.y = acc[mt][nt][half * 2 + 1] * scale;
                *(float2*)&dst[((size_t)h * NPAD + row) * DH + d] = v;
            }
        }
}

// ---- proj (MT=2): grid (8, 26), packed A from combine ----
__global__ __launch_bounds__(256, 2) void gemm_proj_kern(
    const float* __restrict__ bias, float* __restrict__ C)
{
    const int bm = blockIdx.y * 64;
    const int bn = blockIdx.x * 128;
    float acc[2][4][4];
#pragma unroll
    for (int a = 0; a < 2; a++)
#pragma unroll
        for (int b = 0; b < 4; b++)
#pragma unroll
            for (int cc = 0; cc < 4; cc++) acc[a][b][cc] = 0.0f;

    gemm3bp<2>((const uint4*)g_ath, (const uint4*)g_atl,
               (const uint4*)g_wph, (const uint4*)g_wpl,
               bm, bn, (uint32_t*)dynsm, acc);

    const int tid = threadIdx.x;
    const int wid = tid >> 5, lane = tid & 31;
    const int warp_m = wid & 1, warp_n = wid >> 1;
    const int grp = lane >> 2, tig = lane & 3;

#pragma unroll
    for (int mt = 0; mt < 2; ++mt)
#pragma unroll
        for (int half = 0; half < 2; ++half) {
            const int row = bm + warp_m * 32 + mt * 16 + grp + half * 8;
            if (row >= NSEQ) continue;
#pragma unroll
            for (int nt = 0; nt < 4; ++nt) {
                const int col = bn + warp_n * 32 + nt * 8 + tig * 2;
                float2 v;
                v.x = acc[mt][nt][half * 2 + 0] + bias[col];
                v.y = acc[mt][nt][half * 2 + 1] + bias[col + 1];
                *(float2*)&C[(size_t)row * 1024 + col] = v;
            }
        }
}

// ============================================================
// RoPE + pack: reads fp32 q/k, writes packed bf16x2 hi/lo.
// Covers ALL NPAD rows (identity outside rope window; pad rows are 0).
// One thread per (n, h, i<16): d pairs (2i,2i+1) and (2i+32,2i+33).
// ============================================================
__global__ void rope_pack_kern(const float* __restrict__ rope)
{
    const int idx = blockIdx.x * blockDim.x + threadIdx.x;
    if (idx >= NPAD * NH * 16) return;
    const int i = idx & 15;
    const int h = (idx >> 4) & 15;
    const int n = idx >> 8;

    const size_t base = ((size_t)h * NPAD + n) * 64;
    float2 qa = *(const float2*)&g_q[base + 2 * i];
    float2 qb = *(const float2*)&g_q[base + 2 * i + 32];
    float2 ka = *(const float2*)&g_k[base + 2 * i];
    float2 kb = *(const float2*)&g_k[base + 2 * i + 32];

    if ((unsigned)(n - PREFIX) < HWLEN) {
        const int p = n - PREFIX;
        const float2 sa = *(const float2*)&rope[(size_t)p * 64 + 2 * i];
        const float2 sb = *(const float2*)&rope[(size_t)p * 64 + 2 * i + 32];
        const float2 ca = *(const float2*)&rope[(size_t)HWLEN * 64 + (size_t)p * 64 + 2 * i];
        const float2 cb = *(const float2*)&rope[(size_t)HWLEN * 64 + (size_t)p * 64 + 2 * i + 32];
        float2 ra, rb;
        ra.x = qa.x * ca.x - qb.x * sa.x;  rb.x = qb.x * cb.x + qa.x * sb.x;
        ra.y = qa.y * ca.y - qb.y * sa.y;  rb.y = qb.y * cb.y + qa.y * sb.y;
        qa = ra; qb = rb;
        ra.x = ka.x * ca.x - kb.x * sa.x;  rb.x = kb.x * cb.x + ka.x * sb.x;
        ra.y = ka.y * ca.y - kb.y * sa.y;  rb.y = kb.y * cb.y + ka.y * sb.y;
        ka = ra; kb = rb;
    }

    const size_t ob = ((size_t)h * NPAD + n) * 32;
    uint32_t hh, ll;
    split2(qa.x, qa.y, hh, ll); g_qph[ob + i] = hh;      g_qpl[ob + i] = ll;
    split2(qb.x, qb.y, hh, ll); g_qph[ob + 16 + i] = hh; g_qpl[ob + 16 + i] = ll;
    split2(ka.x, ka.y, hh, ll); g_kph[ob + i] = hh;      g_kpl[ob + i] = ll;
    split2(kb.x, kb.y, hh, ll); g_kph[ob + 16 + i] = hh; g_kpl[ob + 16 + i] = ll;
}

// ============================================================
// Flash attention: split-K, bf16x3, pre-packed Q/K (copies only),
// V split in-kernel (key-pair packing). grid (13, 16, 2), 128 thr.
// ============================================================
#define AQ_H 0
#define AQ_L 4608
#define AK_H 9216
#define AK_L 10368
#define AV_H 11520
#define AV_L 12800
#define AP   14080
#define ATTN_SMEM_BYTES (16640 * 4)

__global__ __launch_bounds__(128, 3) void attn_bf16()
{
    uint32_t* usm = (uint32_t*)dynsm;
    uint32_t* Qh = usm + AQ_H;
    uint32_t* Ql = usm + AQ_L;
    uint32_t* Kh = usm + AK_H;
    uint32_t* Kl = usm + AK_L;
    uint32_t* Vh = usm + AV_H;
    uint32_t* Vl = usm + AV_L;

    const int h  = blockIdx.y;
    const int z  = blockIdx.z;
    const int qb = blockIdx.x * 128;
    const int tid = threadIdx.x;
    const int wid = tid >> 5, lane = tid & 31;
    const int grp = lane >> 2, tig = lane & 3;
    const int row0 = wid * 32;

    const int ktb = z * NKT0;
    const int kte = (z == 0) ? NKT0 : NKT_TOT;

    uint32_t* Ph = usm + AP + wid * 640;
    uint32_t* Pl = Ph + 320;

    const uint32_t smb = cvta_s(usm);
    const int q_lm  = AQ_H + (row0 + (lane & 15)) * 36 + (lane >> 4) * 4;
    const int q_lml = q_lm + 4608;
    const int k_lm  = AK_H + ((lane >> 4) * 8 + (lane & 7)) * 36 + ((lane >> 3) & 1) * 4;
    const int k_lml = k_lm + 1152;
    const int v_lm  = AV_H + ((lane >> 4) * 8 + (lane & 7)) * 20 + ((lane >> 3) & 1) * 4;
    const int v_lml = v_lm + 1280;
    const int p_lm  = AP + wid * 640 + (lane & 15) * 20 + (lane >> 4) * 4;
    const int p_lml = p_lm + 320;

    const uint4* __restrict__ Qh4 = (const uint4*)g_qph + ((size_t)h * NPAD + qb) * 8;
    const uint4* __restrict__ Ql4 = (const uint4*)g_qpl + ((size_t)h * NPAD + qb) * 8;
    const uint4* __restrict__ Kh4 = (const uint4*)g_kph + (size_t)h * NPAD * 8;
    const uint4* __restrict__ Kl4 = (const uint4*)g_kpl + (size_t)h * NPAD * 8;
    const float* __restrict__ Vg  = g_v + (size_t)h * NPAD * DH;

    // ---- prologue: Q tile 128x64, straight packed copy ----
#pragma unroll
    for (int t = 0; t < 8; ++t) {
        const int idx = tid + t * 128;
        const int r = idx >> 3, u = idx & 7;
        *(uint4*)(Qh + r * 36 + u * 4) = Qh4[(size_t)r * 8 + u];
        *(uint4*)(Ql + r * 36 + u * 4) = Ql4[(size_t)r * 8 + u];
    }

    const int kr = tid >> 2;             // K row 0..31
    const int ku = tid & 3;              // uint4 slot (x2)
    const int vp = tid & 15;
    const int vdg = tid >> 4;
    uint4 pkh0, pkh1, pkl0, pkl1;
    float4 ve0, ve1, vo0, vo1;

#define KV_FETCH(base) do { \
    pkh0 = Kh4[(size_t)((base) + kr) * 8 + ku]; \
    pkh1 = Kh4[(size_t)((base) + kr) * 8 + 4 + ku]; \
    pkl0 = Kl4[(size_t)((base) + kr) * 8 + ku]; \
    pkl1 = Kl4[(size_t)((base) + kr) * 8 + 4 + ku]; \
    ve0 = *(const float4*)(Vg + (size_t)((base) + 2 * vp) * DH + vdg * 8); \
    ve1 = *(const float4*)(Vg + (size_t)((base) + 2 * vp) * DH + vdg * 8 + 4); \
    vo0 = *(const float4*)(Vg + (size_t)((base) + 2 * vp + 1) * DH + vdg * 8); \
    vo1 = *(const float4*)(Vg + (size_t)((base) + 2 * vp + 1) * DH + vdg * 8 + 4); \
} while (0)

#define KV_STORE() do { \
    *(uint4*)(Kh + kr * 36 + ku * 4) = pkh0; \
    *(uint4*)(Kh + kr * 36 + 16 + ku * 4) = pkh1; \
    *(uint4*)(Kl + kr * 36 + ku * 4) = pkl0; \
    *(uint4*)(Kl + kr * 36 + 16 + ku * 4) = pkl1; \
    { \
        float ve[8] = {ve0.x, ve0.y, ve0.z, ve0.w, ve1.x, ve1.y, ve1.z, ve1.w}; \
        float vo[8] = {vo0.x, vo0.y, vo0.z, vo0.w, vo1.x, vo1.y, vo1.z, vo1.w}; \
        _Pragma("unroll") \
        for (int jj = 0; jj < 8; ++jj) { \
            const int d = vdg * 8 + jj; \
            uint32_t hh, ll; \
            split2(ve[jj], vo[jj], hh, ll); \
            Vh[d * 20 + vp] = hh; \
            Vl[d * 20 + vp] = ll; \
        } \
    } \
} while (0)

    KV_FETCH(ktb * 32);
    KV_STORE();
    __syncthreads();

    float mreg[2][2], lreg[2][2];
#pragma unroll
    for (int mt = 0; mt < 2; ++mt) {
        mreg[mt][0] = -1e38f; mreg[mt][1] = -1e38f;
        lreg[mt][0] = 0.0f;   lreg[mt][1] = 0.0f;
    }
    float o[2][8][4];
#pragma unroll
    for (int mt = 0; mt < 2; mt++)
#pragma unroll
        for (int nt = 0; nt < 8; nt++)
#pragma unroll
            for (int i = 0; i < 4; i++) o[mt][nt][i] = 0.0f;

    for (int kt = ktb; kt < kte; ++kt) {
        const int key0 = kt * 32;

        float sacc[2][4][4];
#pragma unroll
        for (int mt = 0; mt < 2; mt++)
#pragma unroll
            for (int nt = 0; nt < 4; nt++)
#pragma unroll
                for (int i = 0; i < 4; i++) sacc[mt][nt][i] = 0.0f;

#pragma unroll
        for (int ks = 0; ks < 4; ++ks) {
            const int kw = ks * 8;
            uint32_t ah[2][4], al[2][4];
#pragma unroll
            for (int mt = 0; mt < 2; ++mt) {
                LDSM_X4(ah[mt][0], ah[mt][1], ah[mt][2], ah[mt][3],
                        smb + (uint32_t)(q_lm + mt * 576 + kw) * 4u);
                LDSM_X4(al[mt][0], al[mt][1], al[mt][2], al[mt][3],
                        smb + (uint32_t)(q_lml + mt * 576 + kw) * 4u);
            }
#pragma unroll
            for (int ntp = 0; ntp < 2; ++ntp) {
                uint32_t bh0, bh1, bh2, bh3, bl0, bl1, bl2, bl3;
                LDSM_X4(bh0, bh1, bh2, bh3,
                        smb + (uint32_t)(k_lm + ntp * 16 * 36 + kw) * 4u);
                LDSM_X4(bl0, bl1, bl2, bl3,
                        smb + (uint32_t)(k_lml + ntp * 16 * 36 + kw) * 4u);
#pragma unroll
                for (int mt = 0; mt < 2; ++mt) {
                    MMA_BF16(sacc[mt][2 * ntp], ah[mt][0], ah[mt][1], ah[mt][2], ah[mt][3], bh0, bh1);
                    MMA_BF16(sacc[mt][2 * ntp], ah[mt][0], ah[mt][1], ah[mt][2], ah[mt][3], bl0, bl1);
                    MMA_BF16(sacc[mt][2 * ntp], al[mt][0], al[mt][1], al[mt][2], al[mt][3], bh0, bh1);
                    MMA_BF16(sacc[mt][2 * ntp + 1], ah[mt][0], ah[mt][1], ah[mt][2], ah[mt][3], bh2, bh3);
                    MMA_BF16(sacc[mt][2 * ntp + 1], ah[mt][0], ah[mt][1], ah[mt][2], ah[mt][3], bl2, bl3);
                    MMA_BF16(sacc[mt][2 * ntp + 1], al[mt][0], al[mt][1], al[mt][2], al[mt][3], bh2, bh3);
                }
            }
        }

        if (kt + 1 < kte) KV_FETCH((kt + 1) * 32);

#pragma unroll
        for (int mt = 0; mt < 2; ++mt) {
            float mx0 = -1e30f, mx1 = -1e30f;
#pragma unroll
            for (int nt = 0; nt < 4; ++nt) {
                const int c0 = key0 + nt * 8 + tig * 2;
                if (c0 >= NSEQ)     { sacc[mt][nt][0] = -1e30f; sacc[mt][nt][2] = -1e30f; }
                if (c0 + 1 >= NSEQ) { sacc[mt][nt][1] = -1e30f; sacc[mt][nt][3] = -1e30f; }
                mx0 = fmaxf(mx0, fmaxf(sacc[mt][nt][0], sacc[mt][nt][1]));
                mx1 = fmaxf(mx1, fmaxf(sacc[mt][nt][2], sacc[mt][nt][3]));
            }
            mx0 = fmaxf(mx0, __shfl_xor_sync(0xffffffffu, mx0, 1));
            mx0 = fmaxf(mx0, __shfl_xor_sync(0xffffffffu, mx0, 2));
            mx1 = fmaxf(mx1, __shfl_xor_sync(0xffffffffu, mx1, 1));
            mx1 = fmaxf(mx1, __shfl_xor_sync(0xffffffffu, mx1, 2));

            const float mn0 = fmaxf(mreg[mt][0], mx0);
            const float mn1 = fmaxf(mreg[mt][1], mx1);
            const float a0 = __expf(mreg[mt][0] - mn0);
            const float a1 = __expf(mreg[mt][1] - mn1);
            mreg[mt][0] = mn0; mreg[mt][1] = mn1;

            float s0 = 0.0f, s1 = 0.0f;
#pragma unroll
            for (int nt = 0; nt < 4; ++nt) {
                sacc[mt][nt][0] = __expf(sacc[mt][nt][0] - mn0); s0 += sacc[mt][nt][0];
                sacc[mt][nt][1] = __expf(sacc[mt][nt][1] - mn0); s0 += sacc[mt][nt][1];
                sacc[mt][nt][2] = __expf(sacc[mt][nt][2] - mn1); s1 += sacc[mt][nt][2];
                sacc[mt][nt][3] = __expf(sacc[mt][nt][3] - mn1); s1 += sacc[mt][nt][3];
            }
            s0 += __shfl_xor_sync(0xffffffffu, s0, 1);
            s0 += __shfl_xor_sync(0xffffffffu, s0, 2);
            s1 += __shfl_xor_sync(0xffffffffu, s1, 1);
            s1 += __shfl_xor_sync(0xffffffffu, s1, 2);
            lreg[mt][0] = lreg[mt][0] * a0 + s0;
            lreg[mt][1] = lreg[mt][1] * a1 + s1;

#pragma unroll
            for (int nt = 0; nt < 4; ++nt) {
                const int cw = nt * 4 + tig;
                uint32_t hh, ll;
                split2(sacc[mt][nt][0], sacc[mt][nt][1], hh, ll);
                Ph[grp * 20 + cw] = hh; Pl[grp * 20 + cw] = ll;
                split2(sacc[mt][nt][2], sacc[mt][nt][3], hh, ll);
                Ph[(grp + 8) * 20 + cw] = hh; Pl[(grp + 8) * 20 + cw] = ll;
            }

#pragma unroll
            for (int nt = 0; nt < 8; ++nt) {
                o[mt][nt][0] *= a0; o[mt][nt][1] *= a0;
                o[mt][nt][2] *= a1; o[mt][nt][3] *= a1;
            }
            __syncwarp();

#pragma unroll
            for (int kk = 0; kk < 2; ++kk) {
                const int kw = kk * 8;
                uint32_t ph0, ph1, ph2, ph3, pl0, pl1, pl2, pl3;
                LDSM_X4(ph0, ph1, ph2, ph3, smb + (uint32_t)(p_lm + kw) * 4u);
                LDSM_X4(pl0, pl1, pl2, pl3, smb + (uint32_t)(p_lml + kw) * 4u);
#pragma unroll
                for (int ntp = 0; ntp < 4; ++ntp) {
                    uint32_t vh0, vh1, vh2, vh3, vl0, vl1, vl2, vl3;
                    LDSM_X4(vh0, vh1, vh2, vh3,
                            smb + (uint32_t)(v_lm + ntp * 16 * 20 + kw) * 4u);
                    LDSM_X4(vl0, vl1, vl2, vl3,
                            smb + (uint32_t)(v_lml + ntp * 16 * 20 + kw) * 4u);
                    MMA_BF16(o[mt][2 * ntp], ph0, ph1, ph2, ph3, vh0, vh1);
                    MMA_BF16(o[mt][2 * ntp], ph0, ph1, ph2, ph3, vl0, vl1);
                    MMA_BF16(o[mt][2 * ntp], pl0, pl1, pl2, pl3, vh0, vh1);
                    MMA_BF16(o[mt][2 * ntp + 1], ph0, ph1, ph2, ph3, vh2, vh3);
                    MMA_BF16(o[mt][2 * ntp + 1], ph0, ph1, ph2, ph3, vl2, vl3);
                    MMA_BF16(o[mt][2 * ntp + 1], pl0, pl1, pl2, pl3, vh2, vh3);
                }
            }
            if (mt == 0) __syncwarp();
        }
        __syncthreads();

        if (kt + 1 < kte) {
            KV_STORE();
            __syncthreads();
        }
    }

    float* __restrict__ part = g_part + (size_t)(z * NH + h) * NPAD * DH;
    float2* __restrict__ mlp = g_ml + (size_t)(z * NH + h) * NPAD;
#pragma unroll
    for (int mt = 0; mt < 2; ++mt) {
        const float inv0 = 1.0f / lreg[mt][0];
        const float inv1 = 1.0f / lreg[mt][1];
        const int n0 = qb + row0 + mt * 16 + grp;
        const int n1 = n0 + 8;
        if (tig == 0) {
            if (n0 < NSEQ) mlp[n0] = make_float2(mreg[mt][0], lreg[mt][0]);
            if (n1 < NSEQ) mlp[n1] = make_float2(mreg[mt][1], lreg[mt][1]);
        }
#pragma unroll
        for (int nt = 0; nt < 8; ++nt) {
            const int col = nt * 8 + tig * 2;
            if (n0 < NSEQ)
                *(float2*)&part[(size_t)n0 * DH + col] =
                    make_float2(o[mt][nt][0] * inv0, o[mt][nt][1] * inv0);
            if (n1 < NSEQ)
                *(float2*)&part[(size_t)n1 * DH + col] =
                    make_float2(o[mt][nt][2] * inv1, o[mt][nt][3] * inv1);
        }
    }
}

// ============================================================
// Combine split-K partials -> PACKED attn output (for proj)
// ============================================================
__global__ void attn_combine()
{
    const int t = blockIdx.x * blockDim.x + threadIdx.x;
    if (t >= NH * NSEQ * 8) return;
    const int d8 = (t & 7) * 8;
    const int n = (t >> 3) % NSEQ;
    const int h = t / (8 * NSEQ);

    const float2 ml0 = g_ml[(size_t)(0 * NH + h) * NPAD + n];
    const float2 ml1 = g_ml[(size_t)(1 * NH + h) * NPAD + n];
    const float m = fmaxf(ml0.x, ml1.x);
    float w0 = ml0.y * __expf(ml0.x - m);
    float w1 = ml1.y * __expf(ml1.x - m);
    const float inv = 1.0f / (w0 + w1);
    w0 *= inv; w1 *= inv;

    const float* p0 = &g_part[((size_t)(0 * NH + h) * NPAD + n) * DH + d8];
    const float* p1 = &g_part[((size_t)(1 * NH + h) * NPAD + n) * DH + d8];
    const float4 a0 = *(const float4*)p0;
    const float4 a1 = *(const float4*)(p0 + 4);
    const float4 b0 = *(const float4*)p1;
    const float4 b1 = *(const float4*)(p1 + 4);

    float4 r0, r1;
    r0.x = w0 * a0.x + w1 * b0.x;  r0.y = w0 * a0.y + w1 * b0.y;
    r0.z = w0 * a0.z + w1 * b0.z;  r0.w = w0 * a0.w + w1 * b0.w;
    r1.x = w0 * a1.x + w1 * b1.x;  r1.y = w0 * a1.y + w1 * b1.y;
    r1.z = w0 * a1.z + w1 * b1.z;  r1.w = w0 * a1.w + w1 * b1.w;

    uint32_t h0,l0,h1,l1,h2,l2,h3,l3;
    split2(r0.x, r0.y, h0, l0);
    split2(r0.z, r0.w, h1, l1);
    split2(r1.x, r1.y, h2, l2);
    split2(r1.z, r1.w, h3, l3);
    const size_t gi = (size_t)n * 128 + h * 8 + (d8 >> 3);
    ((uint4*)g_ath)[gi] = make_uint4(h0, h1, h2, h3);
    ((uint4*)g_atl)[gi] = make_uint4(l0, l1, l2, l3);
}

// ============================================================
extern "C" void kernel_launch(void* const* d_in, const int* in_sizes, int n_in,
                              void* d_out, int out_size)
{
    (void)in_sizes; (void)n_in; (void)out_size;
    const float* x     = (const float*)d_in[0];
    const float* rope  = (const float*)d_in[1];
    const float* Wqkv  = (const float*)d_in[2];
    const float* Wproj = (const float*)d_in[3];
    const float* bproj = (const float*)d_in[4];
    float* out = (float*)d_out;

    static int configured = 0;
    if (!configured) {
        cudaFuncSetAttribute(gemm_qkv_kern,  cudaFuncAttributeMaxDynamicSharedMemorySize, GSMEM_128);
        cudaFuncSetAttribute(gemm_proj_kern, cudaFuncAttributeMaxDynamicSharedMemorySize, GSMEM_64);
        cudaFuncSetAttribute(attn_bf16,      cudaFuncAttributeMaxDynamicSharedMemorySize, ATTN_SMEM_BYTES);
        configured = 1;
    }

    presplit_kern<<<(PS_TOT + 255) / 256, 256>>>(x, Wqkv, Wproj);
    gemm_qkv_kern<<<dim3(24, 13), 256, GSMEM_128>>>();
    rope_pack_kern<<<(NPAD * NH * 16 + 255) / 256, 256>>>(rope);
    attn_bf16<<<dim3(13, NH, NSPLIT), 128, ATTN_SMEM_BYTES>>>();
    attn_combine<<<(NH * NSEQ * 8 + 255) / 256, 256>>>();
    gemm_proj_kern<<<dim3(8, 26), 256, GSMEM_64>>>(bproj, out);
}